// round 3
// baseline (speedup 1.0000x reference)
#include <cuda_runtime.h>

#define N_NODES 100000
#define E_EDGES 3200000
#define F 64
#define F4 16
#define SCAN_T 1024
#define CHUNK ((N_NODES + SCAN_T - 1) / SCAN_T)   // 98

// Scratch (allocation-free rule: __device__ globals)
__device__ float g_buf1[N_NODES * F];
__device__ float g_buf2[N_NODES * F];
__device__ float g_dinv[N_NODES];
__device__ int   g_cnt[N_NODES];      // in-degree (no self-loop)
__device__ int   g_ptr[N_NODES + 1];  // CSR row pointers (by dst)
__device__ int   g_cur[N_NODES];      // fill cursors
__device__ int   g_csr_src[E_EDGES];  // src ids grouped by dst

__global__ void k_zero_cnt() {
    int i = blockIdx.x * blockDim.x + threadIdx.x;
    if (i < N_NODES) g_cnt[i] = 0;
}

__global__ void k_count(const int* __restrict__ dst) {
    int e = blockIdx.x * blockDim.x + threadIdx.x;
    if (e < E_EDGES) atomicAdd(&g_cnt[dst[e]], 1);
}

// Single-block exclusive scan over g_cnt -> g_ptr/g_cur, plus dinv.
__global__ __launch_bounds__(SCAN_T)
void k_scan() {
    __shared__ int part[SCAN_T];
    int t = threadIdx.x;
    int lo = t * CHUNK;
    int hi = min(lo + CHUNK, N_NODES);
    int s = 0;
    for (int i = lo; i < hi; i++) s += g_cnt[i];
    part[t] = s;
    __syncthreads();
    // Hillis-Steele inclusive scan over 1024 partials
    for (int off = 1; off < SCAN_T; off <<= 1) {
        int v = part[t];
        int u = (t >= off) ? part[t - off] : 0;
        __syncthreads();
        part[t] = v + u;
        __syncthreads();
    }
    int run = (t == 0) ? 0 : part[t - 1];  // exclusive base for this chunk
    for (int i = lo; i < hi; i++) {
        int c = g_cnt[i];
        g_ptr[i] = run;
        g_cur[i] = run;
        g_dinv[i] = rsqrtf((float)(c + 1));   // +1 self-loop
        run += c;
    }
    if (t == SCAN_T - 1) g_ptr[N_NODES] = run;
}

__global__ void k_fill(const int* __restrict__ src,
                       const int* __restrict__ dst) {
    int e = blockIdx.x * blockDim.x + threadIdx.x;
    if (e >= E_EDGES) return;
    int pos = atomicAdd(&g_cur[dst[e]], 1);
    g_csr_src[pos] = src[e];
}

// GEMM, 2 rows per thread: acc in regs, W staged in shared.
// Epilogue scales each row by dinv[row] (hs = (X@W) * dinv).
template<int K>
__global__ __launch_bounds__(128)
void k_gemm2(const float* __restrict__ X,
             const float* __restrict__ W,
             float* __restrict__ out) {
    __shared__ float4 Ws[K * F4];
    for (int t = threadIdx.x; t < K * F4; t += 128)
        Ws[t] = reinterpret_cast<const float4*>(W)[t];
    __syncthreads();

    int r0 = blockIdx.x * 256 + threadIdx.x;
    int r1 = r0 + 128;
    if (r0 >= N_NODES) return;
    bool has1 = (r1 < N_NODES);

    float acc0[F], acc1[F];
#pragma unroll
    for (int j = 0; j < F; j++) { acc0[j] = 0.f; acc1[j] = 0.f; }

    const float4* x0 = reinterpret_cast<const float4*>(X + (size_t)r0 * K);
    const float4* x1 = reinterpret_cast<const float4*>(X + (size_t)(has1 ? r1 : r0) * K);

    for (int k4 = 0; k4 < K / 4; k4++) {
        float4 av = x0[k4];
        float4 bv = x1[k4];
        float as[4] = {av.x, av.y, av.z, av.w};
        float bs[4] = {bv.x, bv.y, bv.z, bv.w};
#pragma unroll
        for (int kk = 0; kk < 4; kk++) {
            float a = as[kk], b = bs[kk];
#pragma unroll
            for (int j4 = 0; j4 < F4; j4++) {
                float4 w = Ws[(k4 * 4 + kk) * F4 + j4];
                acc0[j4 * 4 + 0] += a * w.x;  acc1[j4 * 4 + 0] += b * w.x;
                acc0[j4 * 4 + 1] += a * w.y;  acc1[j4 * 4 + 1] += b * w.y;
                acc0[j4 * 4 + 2] += a * w.z;  acc1[j4 * 4 + 2] += b * w.z;
                acc0[j4 * 4 + 3] += a * w.w;  acc1[j4 * 4 + 3] += b * w.w;
            }
        }
    }

    float s0 = g_dinv[r0];
    float4* o0 = reinterpret_cast<float4*>(out + (size_t)r0 * F);
#pragma unroll
    for (int j4 = 0; j4 < F4; j4++)
        o0[j4] = make_float4(acc0[j4*4+0]*s0, acc0[j4*4+1]*s0,
                             acc0[j4*4+2]*s0, acc0[j4*4+3]*s0);
    if (has1) {
        float s1 = g_dinv[r1];
        float4* o1 = reinterpret_cast<float4*>(out + (size_t)r1 * F);
#pragma unroll
        for (int j4 = 0; j4 < F4; j4++)
            o1[j4] = make_float4(acc1[j4*4+0]*s1, acc1[j4*4+1]*s1,
                                 acc1[j4*4+2]*s1, acc1[j4*4+3]*s1);
    }
}

// CSR gather-aggregate with fused finalize:
// out[n] = (relu?)( dinv[n] * (hs[n] + sum_{e in CSR[n]} hs[src_e]) + bias )
// 16 threads per node; lane c owns float4 chunk c. Edge ids batch-loaded
// coalesced (16 at a time) and broadcast via half-warp shuffles.
template<bool RELU>
__global__ __launch_bounds__(256)
void k_aggregate(const float4* __restrict__ hs,
                 const float* __restrict__ bias,
                 float4* __restrict__ outv) {
    int tid   = threadIdx.x;
    int lane  = tid & 31;
    int c     = tid & 15;                       // chunk within node row
    int group = tid >> 4;                       // 0..15 within block
    int n     = blockIdx.x * 16 + group;
    if (n >= N_NODES) return;
    unsigned mask = 0xFFFFu << (lane & 16);     // half-warp shuffle mask

    int start = g_ptr[n];
    int end   = g_ptr[n + 1];

    // self-loop message
    float4 a = hs[n * 16 + c];
    float accx = a.x, accy = a.y, accz = a.z, accw = a.w;

    for (int j0 = start; j0 < end; j0 += 16) {
        int cnt = min(16, end - j0);
        int myidx = (c < cnt) ? g_csr_src[j0 + c] : 0;
#pragma unroll
        for (int k = 0; k < 16; k++) {
            if (k >= cnt) break;
            int s = __shfl_sync(mask, myidx, k, 16);
            float4 v = __ldg(&hs[s * 16 + c]);
            accx += v.x; accy += v.y; accz += v.z; accw += v.w;
        }
    }

    float d = g_dinv[n];
    float4 b = reinterpret_cast<const float4*>(bias)[c];
    float4 r;
    r.x = fmaf(d, accx, b.x);
    r.y = fmaf(d, accy, b.y);
    r.z = fmaf(d, accz, b.z);
    r.w = fmaf(d, accw, b.w);
    if (RELU) {
        r.x = fmaxf(r.x, 0.f); r.y = fmaxf(r.y, 0.f);
        r.z = fmaxf(r.z, 0.f); r.w = fmaxf(r.w, 0.f);
    }
    outv[n * 16 + c] = r;
}

extern "C" void kernel_launch(void* const* d_in, const int* in_sizes, int n_in,
                              void* d_out, int out_size) {
    const float* x   = (const float*)d_in[0];
    const int*   src = (const int*)d_in[1];
    const int*   dst = (const int*)d_in[1] + E_EDGES;
    const float* W1  = (const float*)d_in[2];
    const float* b1  = (const float*)d_in[3];
    const float* W2  = (const float*)d_in[4];
    const float* b2  = (const float*)d_in[5];
    float* out = (float*)d_out;

    float *buf1 = nullptr, *buf2 = nullptr;
    cudaGetSymbolAddress((void**)&buf1, g_buf1);
    cudaGetSymbolAddress((void**)&buf2, g_buf2);

    const int TB = 256;
    const int nb_nodes = (N_NODES + TB - 1) / TB;
    const int nb_edges = (E_EDGES + TB - 1) / TB;
    const int nb_gemm  = (N_NODES + 255) / 256;
    const int nb_agg   = (N_NODES + 15) / 16;

    // CSR build (by dst) + dinv
    k_zero_cnt<<<nb_nodes, TB>>>();
    k_count<<<nb_edges, TB>>>(dst);
    k_scan<<<1, SCAN_T>>>();
    k_fill<<<nb_edges, TB>>>(src, dst);

    // Layer 1: hs1 = (x @ W1)*dinv -> buf1 ; a1 = agg+relu -> buf2
    k_gemm2<128><<<nb_gemm, 128>>>(x, W1, buf1);
    k_aggregate<true><<<nb_agg, TB>>>((const float4*)buf1, b1, (float4*)buf2);

    // Layer 2: hs2 = (a1 @ W2)*dinv -> buf1 ; out = agg -> d_out
    k_gemm2<64><<<nb_gemm, 128>>>(buf2, W2, buf1);
    k_aggregate<false><<<nb_agg, TB>>>((const float4*)buf1, b2, (float4*)out);
}

// round 4
// speedup vs baseline: 1.0598x; 1.0598x over previous
#include <cuda_runtime.h>

#define N_NODES 100000
#define E_EDGES 3200000
#define F 64
#define F4 16
#define SCAN_T 1024
#define CHUNK ((N_NODES + SCAN_T - 1) / SCAN_T)   // 98

// Scratch (allocation-free rule: __device__ globals)
__device__ float g_buf1[N_NODES * F];
__device__ float g_buf2[N_NODES * F];
__device__ float g_dinv[N_NODES];
__device__ int   g_cnt[N_NODES];      // in-degree (no self-loop)
__device__ int   g_ptr[N_NODES + 1];  // CSR row pointers (by dst)
__device__ int   g_cur[N_NODES];      // fill cursors
__device__ int   g_csr_src[E_EDGES];  // src ids grouped by dst

__global__ void k_zero_cnt() {
    int i = blockIdx.x * blockDim.x + threadIdx.x;
    if (i < N_NODES) g_cnt[i] = 0;
}

__global__ void k_count(const int* __restrict__ dst) {
    int e = blockIdx.x * blockDim.x + threadIdx.x;
    if (e < E_EDGES) atomicAdd(&g_cnt[dst[e]], 1);
}

// Single-block exclusive scan over g_cnt -> g_ptr/g_cur, plus dinv.
__global__ __launch_bounds__(SCAN_T)
void k_scan() {
    __shared__ int part[SCAN_T];
    int t = threadIdx.x;
    int lo = t * CHUNK;
    int hi = min(lo + CHUNK, N_NODES);
    int s = 0;
    for (int i = lo; i < hi; i++) s += g_cnt[i];
    part[t] = s;
    __syncthreads();
    // Hillis-Steele inclusive scan over 1024 partials
    for (int off = 1; off < SCAN_T; off <<= 1) {
        int v = part[t];
        int u = (t >= off) ? part[t - off] : 0;
        __syncthreads();
        part[t] = v + u;
        __syncthreads();
    }
    int run = (t == 0) ? 0 : part[t - 1];  // exclusive base for this chunk
    for (int i = lo; i < hi; i++) {
        int c = g_cnt[i];
        g_ptr[i] = run;
        g_cur[i] = run;
        g_dinv[i] = rsqrtf((float)(c + 1));   // +1 self-loop
        run += c;
    }
    if (t == SCAN_T - 1) g_ptr[N_NODES] = run;
}

__global__ void k_fill(const int* __restrict__ src,
                       const int* __restrict__ dst) {
    int e = blockIdx.x * blockDim.x + threadIdx.x;
    if (e >= E_EDGES) return;
    int pos = atomicAdd(&g_cur[dst[e]], 1);
    g_csr_src[pos] = src[e];
}

// GEMM, 2 rows per thread: acc in regs, W staged in shared.
// Epilogue scales each row by dinv[row] (hs = (X@W) * dinv).
template<int K>
__global__ __launch_bounds__(128)
void k_gemm2(const float* __restrict__ X,
             const float* __restrict__ W,
             float* __restrict__ out) {
    __shared__ float4 Ws[K * F4];
    for (int t = threadIdx.x; t < K * F4; t += 128)
        Ws[t] = reinterpret_cast<const float4*>(W)[t];
    __syncthreads();

    int r0 = blockIdx.x * 256 + threadIdx.x;
    int r1 = r0 + 128;
    if (r0 >= N_NODES) return;
    bool has1 = (r1 < N_NODES);

    float acc0[F], acc1[F];
#pragma unroll
    for (int j = 0; j < F; j++) { acc0[j] = 0.f; acc1[j] = 0.f; }

    const float4* x0 = reinterpret_cast<const float4*>(X + (size_t)r0 * K);
    const float4* x1 = reinterpret_cast<const float4*>(X + (size_t)(has1 ? r1 : r0) * K);

    for (int k4 = 0; k4 < K / 4; k4++) {
        float4 av = x0[k4];
        float4 bv = x1[k4];
        float as[4] = {av.x, av.y, av.z, av.w};
        float bs[4] = {bv.x, bv.y, bv.z, bv.w};
#pragma unroll
        for (int kk = 0; kk < 4; kk++) {
            float a = as[kk], b = bs[kk];
#pragma unroll
            for (int j4 = 0; j4 < F4; j4++) {
                float4 w = Ws[(k4 * 4 + kk) * F4 + j4];
                acc0[j4 * 4 + 0] += a * w.x;  acc1[j4 * 4 + 0] += b * w.x;
                acc0[j4 * 4 + 1] += a * w.y;  acc1[j4 * 4 + 1] += b * w.y;
                acc0[j4 * 4 + 2] += a * w.z;  acc1[j4 * 4 + 2] += b * w.z;
                acc0[j4 * 4 + 3] += a * w.w;  acc1[j4 * 4 + 3] += b * w.w;
            }
        }
    }

    float s0 = g_dinv[r0];
    float4* o0 = reinterpret_cast<float4*>(out + (size_t)r0 * F);
#pragma unroll
    for (int j4 = 0; j4 < F4; j4++)
        o0[j4] = make_float4(acc0[j4*4+0]*s0, acc0[j4*4+1]*s0,
                             acc0[j4*4+2]*s0, acc0[j4*4+3]*s0);
    if (has1) {
        float s1 = g_dinv[r1];
        float4* o1 = reinterpret_cast<float4*>(out + (size_t)r1 * F);
#pragma unroll
        for (int j4 = 0; j4 < F4; j4++)
            o1[j4] = make_float4(acc1[j4*4+0]*s1, acc1[j4*4+1]*s1,
                                 acc1[j4*4+2]*s1, acc1[j4*4+3]*s1);
    }
}

// CSR gather-aggregate with fused finalize:
// out[n] = (relu?)( dinv[n] * (hs[n] + sum_{e in CSR[n]} hs[src_e]) + bias )
// 16 threads per node; lane c owns float4 chunk c. Indices read via
// half-warp-uniform __ldg (L1 broadcast); 16 fully-unrolled predicated
// iterations so the compiler front-batches all loads (MLP ~ 32).
template<bool RELU>
__global__ __launch_bounds__(512)
void k_aggregate(const float4* __restrict__ hs,
                 const float* __restrict__ bias,
                 float4* __restrict__ outv) {
    int tid   = threadIdx.x;
    int c     = tid & 15;                       // chunk within node row
    int group = tid >> 4;                       // 0..31 within block
    int n     = blockIdx.x * 32 + group;
    if (n >= N_NODES) return;

    int start = g_ptr[n];
    int end   = g_ptr[n + 1];

    // self-loop message
    float4 a = hs[n * 16 + c];
    float accx = a.x, accy = a.y, accz = a.z, accw = a.w;

    for (int j0 = start; j0 < end; j0 += 16) {
#pragma unroll
        for (int k = 0; k < 16; k++) {
            if (j0 + k < end) {
                int s = __ldg(&g_csr_src[j0 + k]);   // uniform per half-warp
                float4 v = __ldg(&hs[s * 16 + c]);
                accx += v.x; accy += v.y; accz += v.z; accw += v.w;
            }
        }
    }

    float d = g_dinv[n];
    float4 b = reinterpret_cast<const float4*>(bias)[c];
    float4 r;
    r.x = fmaf(d, accx, b.x);
    r.y = fmaf(d, accy, b.y);
    r.z = fmaf(d, accz, b.z);
    r.w = fmaf(d, accw, b.w);
    if (RELU) {
        r.x = fmaxf(r.x, 0.f); r.y = fmaxf(r.y, 0.f);
        r.z = fmaxf(r.z, 0.f); r.w = fmaxf(r.w, 0.f);
    }
    outv[n * 16 + c] = r;
}

extern "C" void kernel_launch(void* const* d_in, const int* in_sizes, int n_in,
                              void* d_out, int out_size) {
    const float* x   = (const float*)d_in[0];
    const int*   src = (const int*)d_in[1];
    const int*   dst = (const int*)d_in[1] + E_EDGES;
    const float* W1  = (const float*)d_in[2];
    const float* b1  = (const float*)d_in[3];
    const float* W2  = (const float*)d_in[4];
    const float* b2  = (const float*)d_in[5];
    float* out = (float*)d_out;

    float *buf1 = nullptr, *buf2 = nullptr;
    cudaGetSymbolAddress((void**)&buf1, g_buf1);
    cudaGetSymbolAddress((void**)&buf2, g_buf2);

    const int TB = 256;
    const int nb_nodes = (N_NODES + TB - 1) / TB;
    const int nb_edges = (E_EDGES + TB - 1) / TB;
    const int nb_gemm  = (N_NODES + 255) / 256;
    const int nb_agg   = (N_NODES + 31) / 32;

    // CSR build (by dst) + dinv
    k_zero_cnt<<<nb_nodes, TB>>>();
    k_count<<<nb_edges, TB>>>(dst);
    k_scan<<<1, SCAN_T>>>();
    k_fill<<<nb_edges, TB>>>(src, dst);

    // Layer 1: hs1 = (x @ W1)*dinv -> buf1 ; a1 = agg+relu -> buf2
    k_gemm2<128><<<nb_gemm, 128>>>(x, W1, buf1);
    k_aggregate<true><<<nb_agg, 512>>>((const float4*)buf1, b1, (float4*)buf2);

    // Layer 2: hs2 = (a1 @ W2)*dinv -> buf1 ; out = agg -> d_out
    k_gemm2<64><<<nb_gemm, 128>>>(buf2, W2, buf1);
    k_aggregate<false><<<nb_agg, 512>>>((const float4*)buf1, b2, (float4*)out);
}